// round 1
// baseline (speedup 1.0000x reference)
#include <cuda_runtime.h>
#include <cstdint>

#define BB 4
#define CC 256
#define HH 180
#define WW 320
#define DD 64
#define TX 64            // x-tile per block
#define CH 16            // channels per chunk
#define NCH (CC / CH)    // 16 chunks
#define RW 128           // right window width: [x0-64, x0+64)
#define NTHREADS 128
#define NTILE (WW / TX)  // 5

__device__ __forceinline__ void cpa16(uint32_t dst, const float* src, int srcbytes) {
    asm volatile("cp.async.cg.shared.global [%0], [%1], 16, %2;\n"
                 :: "r"(dst), "l"(src), "r"(srcbytes));
}

__global__ __launch_bounds__(NTHREADS)
void cost_volume_kernel(const float* __restrict__ Lp,
                        const float* __restrict__ Rp,
                        float* __restrict__ out) {
    __shared__ float sL[2][CH][TX];   // 8 KB
    __shared__ float sR[2][CH][RW];   // 16 KB

    const int tid  = threadIdx.x;
    const int bid  = blockIdx.x;
    const int tile = bid % NTILE;
    const int hh   = (bid / NTILE) % HH;
    const int bb   = bid / (NTILE * HH);
    const int x0   = tile * TX;

    const int HW = HH * WW;  // channel stride

    // base row pointers (channel 0)
    const float* Lrow = Lp + ((size_t)bb * CC * HH + hh) * WW + x0;
    const float* Rrow = Rp + ((size_t)bb * CC * HH + hh) * WW + (x0 - 64);

    // ---- loader coordinates (fixed per thread) ----
    // left: 16 rows x 16 float4 = 256 float4, 2 per thread
    int lrow[2], lcol[2];
#pragma unroll
    for (int k = 0; k < 2; k++) {
        int idx = tid + k * NTHREADS;
        lrow[k] = idx >> 4;
        lcol[k] = (idx & 15) * 4;
    }
    // right: 16 rows x 32 float4 = 512 float4, 4 per thread
    int rrow[4], rcol[4];
#pragma unroll
    for (int k = 0; k < 4; k++) {
        int idx = tid + k * NTHREADS;
        rrow[k] = idx >> 5;
        rcol[k] = (idx & 31) * 4;
    }

    // compute mapping: xg in [0,16), ig in [0,8): thread owns x = x0+4*xg+{0..3}, i = 8*ig+{0..7}
    const int xg = tid & 15;
    const int ig = tid >> 4;
    const int k0 = 56 + 4 * xg - 8 * ig;   // aligned right-window base (in floats), in [0,116]

    float acc[8][4];
#pragma unroll
    for (int a = 0; a < 8; a++)
#pragma unroll
        for (int b = 0; b < 4; b++) acc[a][b] = 0.0f;

    // ---- chunk loader ----
    auto load_chunk = [&](int buf, int ch) {
        const float* lb = Lrow + (size_t)(ch * CH) * HW;
        const float* rb = Rrow + (size_t)(ch * CH) * HW;
#pragma unroll
        for (int k = 0; k < 2; k++) {
            uint32_t d = (uint32_t)__cvta_generic_to_shared(&sL[buf][lrow[k]][lcol[k]]);
            cpa16(d, lb + (size_t)lrow[k] * HW + lcol[k], 16);
        }
#pragma unroll
        for (int k = 0; k < 4; k++) {
            uint32_t d = (uint32_t)__cvta_generic_to_shared(&sR[buf][rrow[k]][rcol[k]]);
            int gx = x0 - 64 + rcol[k];
            bool valid = (gx >= 0);          // gx+3 < WW always holds (max 316)
            const float* src = valid ? (rb + (size_t)rrow[k] * HW + rcol[k]) : Rp;
            cpa16(d, src, valid ? 16 : 0);   // src-size 0 -> zero fill (handles x<i padding)
        }
    };

    load_chunk(0, 0);
    asm volatile("cp.async.commit_group;\n" ::: "memory");

    for (int ch = 0; ch < NCH; ch++) {
        if (ch < NCH - 1) {
            load_chunk((ch + 1) & 1, ch + 1);
            asm volatile("cp.async.commit_group;\n" ::: "memory");
            asm volatile("cp.async.wait_group 1;\n" ::: "memory");
        } else {
            asm volatile("cp.async.wait_group 0;\n" ::: "memory");
        }
        __syncthreads();

        const int buf = ch & 1;
#pragma unroll
        for (int j = 0; j < CH; j++) {
            float4 lv4 = *(const float4*)&sL[buf][j][xg * 4];
            float la[4] = {lv4.x, lv4.y, lv4.z, lv4.w};

            float4 r0 = *(const float4*)&sR[buf][j][k0];
            float4 r1 = *(const float4*)&sR[buf][j][k0 + 4];
            float4 r2 = *(const float4*)&sR[buf][j][k0 + 8];
            float rv[12] = {r0.x, r0.y, r0.z, r0.w,
                            r1.x, r1.y, r1.z, r1.w,
                            r2.x, r2.y, r2.z, r2.w};
#pragma unroll
            for (int di = 0; di < 8; di++) {
#pragma unroll
                for (int dx = 0; dx < 4; dx++) {
                    // rv index: 8 + dx - di, in [1, 11]
                    acc[di][dx] = fmaf(la[dx], rv[8 + dx - di], acc[di][dx]);
                }
            }
        }
        __syncthreads();
    }

    // ---- epilogue ----
    const float scale = 1.0f / 256.0f;
    const int x = x0 + xg * 4;
#pragma unroll
    for (int di = 0; di < 8; di++) {
        int i = ig * 8 + di;
        float4 v;
        v.x = acc[di][0] * scale;
        v.y = acc[di][1] * scale;
        v.z = acc[di][2] * scale;
        v.w = acc[di][3] * scale;
        *(float4*)&out[(((size_t)bb * DD + i) * HH + hh) * WW + x] = v;
    }
}

extern "C" void kernel_launch(void* const* d_in, const int* in_sizes, int n_in,
                              void* d_out, int out_size) {
    const float* left  = (const float*)d_in[0];
    const float* right = (const float*)d_in[1];
    float* out = (float*)d_out;
    (void)in_sizes; (void)n_in; (void)out_size;

    dim3 grid(NTILE * HH * BB);   // 3600 blocks
    dim3 block(NTHREADS);
    cost_volume_kernel<<<grid, block>>>(left, right, out);
}

// round 2
// speedup vs baseline: 1.0002x; 1.0002x over previous
#include <cuda_runtime.h>
#include <cstdint>

#define BB 4
#define CC 256
#define HH 180
#define WW 320
#define DD 64
#define TX 64            // x-tile per block
#define CH 16            // channels per chunk
#define NCH (CC / CH)    // 16 chunks
#define RW 128           // right window width: [x0-64, x0+64)
#define NTHREADS 128
#define NTILE (WW / TX)  // 5

__device__ __forceinline__ void cpa16(uint32_t dst, const float* src, int srcbytes) {
    asm volatile("cp.async.cg.shared.global [%0], [%1], 16, %2;\n"
                 :: "r"(dst), "l"(src), "r"(srcbytes));
}

__global__ __launch_bounds__(NTHREADS)
void cost_volume_kernel(const float* __restrict__ Lp,
                        const float* __restrict__ Rp,
                        float* __restrict__ out) {
    __shared__ float sL[2][CH][TX];   // 8 KB
    __shared__ float sR[2][CH][RW];   // 16 KB

    const int tid  = threadIdx.x;
    const int bid  = blockIdx.x;
    const int tile = bid % NTILE;
    const int hh   = (bid / NTILE) % HH;
    const int bb   = bid / (NTILE * HH);
    const int x0   = tile * TX;

    const int HW = HH * WW;  // channel stride

    // base row pointers (channel 0)
    const float* Lrow = Lp + ((size_t)bb * CC * HH + hh) * WW + x0;
    const float* Rrow = Rp + ((size_t)bb * CC * HH + hh) * WW + (x0 - 64);

    // ---- loader coordinates (fixed per thread) ----
    // left: 16 rows x 16 float4 = 256 float4, 2 per thread
    int lrow[2], lcol[2];
#pragma unroll
    for (int k = 0; k < 2; k++) {
        int idx = tid + k * NTHREADS;
        lrow[k] = idx >> 4;
        lcol[k] = (idx & 15) * 4;
    }
    // right: 16 rows x 32 float4 = 512 float4, 4 per thread
    int rrow[4], rcol[4];
#pragma unroll
    for (int k = 0; k < 4; k++) {
        int idx = tid + k * NTHREADS;
        rrow[k] = idx >> 5;
        rcol[k] = (idx & 31) * 4;
    }

    // compute mapping: xg in [0,16), ig in [0,8): thread owns x = x0+4*xg+{0..3}, i = 8*ig+{0..7}
    const int xg = tid & 15;
    const int ig = tid >> 4;
    const int k0 = 56 + 4 * xg - 8 * ig;   // aligned right-window base (in floats), in [0,116]

    float acc[8][4];
#pragma unroll
    for (int a = 0; a < 8; a++)
#pragma unroll
        for (int b = 0; b < 4; b++) acc[a][b] = 0.0f;

    // ---- chunk loader ----
    auto load_chunk = [&](int buf, int ch) {
        const float* lb = Lrow + (size_t)(ch * CH) * HW;
        const float* rb = Rrow + (size_t)(ch * CH) * HW;
#pragma unroll
        for (int k = 0; k < 2; k++) {
            uint32_t d = (uint32_t)__cvta_generic_to_shared(&sL[buf][lrow[k]][lcol[k]]);
            cpa16(d, lb + (size_t)lrow[k] * HW + lcol[k], 16);
        }
#pragma unroll
        for (int k = 0; k < 4; k++) {
            uint32_t d = (uint32_t)__cvta_generic_to_shared(&sR[buf][rrow[k]][rcol[k]]);
            int gx = x0 - 64 + rcol[k];
            bool valid = (gx >= 0);          // gx+3 < WW always holds (max 316)
            const float* src = valid ? (rb + (size_t)rrow[k] * HW + rcol[k]) : Rp;
            cpa16(d, src, valid ? 16 : 0);   // src-size 0 -> zero fill (handles x<i padding)
        }
    };

    load_chunk(0, 0);
    asm volatile("cp.async.commit_group;\n" ::: "memory");

    for (int ch = 0; ch < NCH; ch++) {
        if (ch < NCH - 1) {
            load_chunk((ch + 1) & 1, ch + 1);
            asm volatile("cp.async.commit_group;\n" ::: "memory");
            asm volatile("cp.async.wait_group 1;\n" ::: "memory");
        } else {
            asm volatile("cp.async.wait_group 0;\n" ::: "memory");
        }
        __syncthreads();

        const int buf = ch & 1;
#pragma unroll
        for (int j = 0; j < CH; j++) {
            float4 lv4 = *(const float4*)&sL[buf][j][xg * 4];
            float la[4] = {lv4.x, lv4.y, lv4.z, lv4.w};

            float4 r0 = *(const float4*)&sR[buf][j][k0];
            float4 r1 = *(const float4*)&sR[buf][j][k0 + 4];
            float4 r2 = *(const float4*)&sR[buf][j][k0 + 8];
            float rv[12] = {r0.x, r0.y, r0.z, r0.w,
                            r1.x, r1.y, r1.z, r1.w,
                            r2.x, r2.y, r2.z, r2.w};
#pragma unroll
            for (int di = 0; di < 8; di++) {
#pragma unroll
                for (int dx = 0; dx < 4; dx++) {
                    // rv index: 8 + dx - di, in [1, 11]
                    acc[di][dx] = fmaf(la[dx], rv[8 + dx - di], acc[di][dx]);
                }
            }
        }
        __syncthreads();
    }

    // ---- epilogue ----
    const float scale = 1.0f / 256.0f;
    const int x = x0 + xg * 4;
#pragma unroll
    for (int di = 0; di < 8; di++) {
        int i = ig * 8 + di;
        float4 v;
        v.x = acc[di][0] * scale;
        v.y = acc[di][1] * scale;
        v.z = acc[di][2] * scale;
        v.w = acc[di][3] * scale;
        *(float4*)&out[(((size_t)bb * DD + i) * HH + hh) * WW + x] = v;
    }
}

extern "C" void kernel_launch(void* const* d_in, const int* in_sizes, int n_in,
                              void* d_out, int out_size) {
    const float* left  = (const float*)d_in[0];
    const float* right = (const float*)d_in[1];
    float* out = (float*)d_out;
    (void)in_sizes; (void)n_in; (void)out_size;

    dim3 grid(NTILE * HH * BB);   // 3600 blocks
    dim3 block(NTHREADS);
    cost_volume_kernel<<<grid, block>>>(left, right, out);
}

// round 7
// speedup vs baseline: 1.9154x; 1.9151x over previous
#include <cuda_runtime.h>
#include <cuda_fp16.h>
#include <cstdint>
#include <cstring>

#define BB 4
#define CC 256
#define HH 180
#define WW 320
#define DD 64
#define HW (HH * WW)

#define XT 128           // M tile (x per CTA)
#define NXT 3            // ceil(320/128)
#define NWIN 192         // y window [x0-64, x0+128)
#define KC 32            // channels per chunk
#define NCHUNK (CC / KC) // 8
#define NTHREADS 256     // 8 warps, warp w -> rows 16w..16w+15

// smem (bytes). k-major, 16B-padded rows for conflict-free ldmatrix
#define SA_STRIDE 272            // 128 halfs + pad = 17 * 16B
#define SB_STRIDE 400            // 192 halfs + pad = 25 * 16B
#define SA_BYTES (KC * SA_STRIDE)        // 8704
#define SB_BYTES (KC * SB_STRIDE)        // 12800
#define SB_BASE (2 * SA_BYTES)           // 17408
#define SMEM_BYTES (2 * SA_BYTES + 2 * SB_BYTES)  // 43008
#define SOUT_STRIDE 132          // floats; 64*132*4 = 33792 <= 43008

static __device__ __forceinline__ uint32_t smem_u32(const void* p) {
    uint32_t a;
    asm("{ .reg .u64 t; cvta.to.shared.u64 t, %1; cvt.u32.u64 %0, t; }"
        : "=r"(a) : "l"(p));
    return a;
}

static __device__ __forceinline__ void ldsm4t(uint32_t& r0, uint32_t& r1,
                                              uint32_t& r2, uint32_t& r3,
                                              uint32_t addr) {
    asm volatile("ldmatrix.sync.aligned.m8n8.x4.trans.shared.b16 {%0,%1,%2,%3}, [%4];"
                 : "=r"(r0), "=r"(r1), "=r"(r2), "=r"(r3) : "r"(addr));
}

static __device__ __forceinline__ void mma16816(float* c,
                                                uint32_t a0, uint32_t a1,
                                                uint32_t a2, uint32_t a3,
                                                uint32_t b0, uint32_t b1) {
    asm volatile("mma.sync.aligned.m16n8k16.row.col.f32.f16.f16.f32 "
                 "{%0,%1,%2,%3},{%4,%5,%6,%7},{%8,%9},{%0,%1,%2,%3};"
                 : "+f"(c[0]), "+f"(c[1]), "+f"(c[2]), "+f"(c[3])
                 : "r"(a0), "r"(a1), "r"(a2), "r"(a3), "r"(b0), "r"(b1));
}

static __device__ __forceinline__ uint32_t pack_h2(float x, float y) {
    __half2 h = __floats2half2_rn(x, y);
    uint32_t u;
    memcpy(&u, &h, 4);
    return u;
}

__global__ __launch_bounds__(NTHREADS)
void cost_volume_hmma(const float* __restrict__ Lp,
                      const float* __restrict__ Rp,
                      float* __restrict__ out) {
    __shared__ __align__(16) char sBuf[SMEM_BYTES];

    const int tid = threadIdx.x;
    const int wid = tid >> 5;
    const int lid = tid & 31;
    const int bid = blockIdx.x;

    const int xtile = bid % NXT;
    const int hh = (bid / NXT) % HH;
    const int bb = bid / (NXT * HH);
    const int x0 = xtile * XT;
    const int y0 = x0 - 64;

    const uint32_t sbase = smem_u32(sBuf);

    const float* Lbase = Lp + (size_t)bb * CC * HW + (size_t)hh * WW;
    const float* Rbase = Rp + (size_t)bb * CC * HW + (size_t)hh * WW;

    // ---- loader coordinates ----
    // A: 32 c-rows x 32 float4 (128 x) = 1024 quads, 4 per thread
    // B: 32 c-rows x 48 float4 (192 y) = 1536 quads, 6 per thread
    const int b_c = tid >> 3;           // 0..31
    const int b_sub = tid & 7;          // 0..7  (quad = b_sub + 8p)

    // ---- ldmatrix per-lane address components ----
    // A frag (trans): row = ks16 + (l&7) + ((l>>4)&1)*8 ; col = 16w + ((l>>3)&1)*8
    const uint32_t a_lrow = (uint32_t)((lid & 7) + ((lid >> 4) & 1) * 8);
    const uint32_t a_lcol = (uint32_t)(16 * wid + ((lid >> 3) & 1) * 8);
    const uint32_t a_loff = a_lrow * SA_STRIDE + a_lcol * 2;
    // B frag (trans): row = ks16 + (l&7) + ((l>>3)&1)*8 ; col = 16w + ((l>>4)&1)*8
    const uint32_t b_lrow = (uint32_t)((lid & 7) + ((lid >> 3) & 1) * 8);
    const uint32_t b_lcol = (uint32_t)(16 * wid + ((lid >> 4) & 1) * 8);
    const uint32_t b_loff = b_lrow * SB_STRIDE + b_lcol * 2;

    float acc[10][4];
#pragma unroll
    for (int t = 0; t < 10; ++t)
#pragma unroll
        for (int j = 0; j < 4; ++j) acc[t][j] = 0.0f;

    float4 aq[4], bq[6];
    const float4 zero4 = make_float4(0.f, 0.f, 0.f, 0.f);

    auto ldg_chunk = [&](int k) {
        const float* Lc = Lbase + (size_t)(k * KC) * HW;
        const float* Rc = Rbase + (size_t)(k * KC) * HW;
#pragma unroll
        for (int p = 0; p < 4; ++p) {
            int q = tid + p * NTHREADS;
            int c = q >> 5, xq = q & 31;
            int x = x0 + xq * 4;
            aq[p] = (x < WW) ? *(const float4*)(Lc + (size_t)c * HW + x) : zero4;
        }
#pragma unroll
        for (int p = 0; p < 6; ++p) {
            int yq = b_sub + p * 8;
            int y = y0 + yq * 4;
            bq[p] = (y >= 0 && y < WW) ? *(const float4*)(Rc + (size_t)b_c * HW + y)
                                       : zero4;
        }
    };

    auto sts_chunk = [&](int buf) {
#pragma unroll
        for (int p = 0; p < 4; ++p) {
            int q = tid + p * NTHREADS;
            int c = q >> 5, xq = q & 31;
            uint2 u;
            u.x = pack_h2(aq[p].x, aq[p].y);
            u.y = pack_h2(aq[p].z, aq[p].w);
            *(uint2*)(sBuf + buf * SA_BYTES + c * SA_STRIDE + xq * 8) = u;
        }
#pragma unroll
        for (int p = 0; p < 6; ++p) {
            int yq = b_sub + p * 8;
            uint2 u;
            u.x = pack_h2(bq[p].x, bq[p].y);
            u.y = pack_h2(bq[p].z, bq[p].w);
            *(uint2*)(sBuf + SB_BASE + buf * SB_BYTES + b_c * SB_STRIDE + yq * 8) = u;
        }
    };

    auto compute = [&](int buf) {
        const uint32_t abase = sbase + (uint32_t)(buf * SA_BYTES) + a_loff;
        const uint32_t bbase = sbase + (uint32_t)(SB_BASE + buf * SB_BYTES) + b_loff;
#pragma unroll
        for (int ks = 0; ks < 2; ++ks) {
            uint32_t a0, a1, a2, a3;
            ldsm4t(a0, a1, a2, a3, abase + (uint32_t)(ks * 16 * SA_STRIDE));
#pragma unroll
            for (int tp = 0; tp < 5; ++tp) {
                uint32_t b0, b1, b2, b3;
                ldsm4t(b0, b1, b2, b3,
                       bbase + (uint32_t)(ks * 16 * SB_STRIDE + tp * 32));
                mma16816(acc[2 * tp],     a0, a1, a2, a3, b0, b1);
                mma16816(acc[2 * tp + 1], a0, a1, a2, a3, b2, b3);
            }
        }
    };

    // ---- pipelined mainloop ----
    ldg_chunk(0);
    sts_chunk(0);
    __syncthreads();
#pragma unroll 1
    for (int k = 0; k < NCHUNK; ++k) {
        if (k + 1 < NCHUNK) ldg_chunk(k + 1);
        compute(k & 1);
        if (k + 1 < NCHUNK) sts_chunk((k + 1) & 1);
        __syncthreads();
    }

    // ---- epilogue: diagonal remap into sOut[i][x], i = x - y ----
    float* sOut = (float*)sBuf;
    const float sc = 1.0f / 256.0f;
    const int g = lid >> 2;
    const int tg = lid & 3;
#pragma unroll
    for (int t = 0; t < 10; ++t) {
#pragma unroll
        for (int j = 0; j < 4; ++j) {
            const int r = g + (j >> 1) * 8;
            const int cn = 2 * tg + (j & 1);
            const int i = r + 64 - 8 * t - cn;   // disparity
            if (i >= 0 && i < DD)
                sOut[i * SOUT_STRIDE + 16 * wid + r] = acc[t][j] * sc;
        }
    }
    __syncthreads();

    // ---- coalesced float4 stores ----
    {
        const int xl4 = lid * 4;
        if (x0 + xl4 < WW) {
#pragma unroll
            for (int i = wid; i < DD; i += 8) {
                float4 v = *(const float4*)&sOut[i * SOUT_STRIDE + xl4];
                *(float4*)&out[(((size_t)bb * DD + i) * HH + hh) * WW + x0 + xl4] = v;
            }
        }
    }
}

extern "C" void kernel_launch(void* const* d_in, const int* in_sizes, int n_in,
                              void* d_out, int out_size) {
    const float* left  = (const float*)d_in[0];
    const float* right = (const float*)d_in[1];
    float* out = (float*)d_out;
    (void)in_sizes; (void)n_in; (void)out_size;

    dim3 grid(NXT * HH * BB);   // 2160 CTAs: xtile fastest -> R-overlap L2 reuse
    dim3 block(NTHREADS);
    cost_volume_hmma<<<grid, block>>>(left, right, out);
}